// round 1
// baseline (speedup 1.0000x reference)
#include <cuda_runtime.h>
#include <cstdint>

#define N_FEAT 512
#define N_PAIRS (N_FEAT * (N_FEAT - 1) / 2)   // 130816
#define TB 8            // batch rows per block
#define THREADS 256
#define PAIRS_PER_THREAD 4
#define PAIRS_PER_BLOCK (THREADS * PAIRS_PER_THREAD)  // 1024

// offset of first pair with row index i in the upper-triangular (k=1) ordering
__device__ __forceinline__ int tri_off(int i) {
    // sum_{r<i} (N_FEAT-1-r) = i*(2*N_FEAT-1-i)/2
    return (i * (2 * N_FEAT - 1 - i)) >> 1;
}

__device__ __forceinline__ void pair_from_p(int p, int& i, int& j) {
    // solve i from p: largest i with tri_off(i) <= p
    float t = (float)N_FEAT - 0.5f;
    float d = t * t - 2.0f * (float)p;
    d = d > 0.0f ? d : 0.0f;
    int ii = (int)floorf(t - sqrtf(d));
    if (ii < 0) ii = 0;
    if (ii > N_FEAT - 2) ii = N_FEAT - 2;
    // exact integer fixup (sqrt error is < 0.1, so at most a step or two)
    while (ii < N_FEAT - 2 && tri_off(ii + 1) <= p) ii++;
    while (ii > 0 && tri_off(ii) > p) ii--;
    i = ii;
    j = ii + 1 + (p - tri_off(ii));
}

__global__ void __launch_bounds__(THREADS, 4)
wide_layer_kernel(const float* __restrict__ x,
                  const float* __restrict__ w,
                  float* __restrict__ out)
{
    __shared__ float xs[TB * N_FEAT];   // 16 KB

    const int tid = threadIdx.x;
    const int b0  = blockIdx.y * TB;

    // cooperative vectorized load of the x tile: TB*512 floats = 1024 float4
    {
        const float4* xg = (const float4*)(x + (size_t)b0 * N_FEAT);
        float4* xsv = (float4*)xs;
        #pragma unroll
        for (int k = 0; k < (TB * N_FEAT / 4) / THREADS; k++)
            xsv[tid + k * THREADS] = xg[tid + k * THREADS];
    }
    __syncthreads();

    const int p0 = blockIdx.x * PAIRS_PER_BLOCK + tid * PAIRS_PER_THREAD;
    if (p0 >= N_PAIRS) return;

    // compute the 4 (i,j) pairs once per thread
    int i0, j0;
    pair_from_p(p0, i0, j0);
    int ia[PAIRS_PER_THREAD], ja[PAIRS_PER_THREAD];
    ia[0] = i0; ja[0] = j0;
    #pragma unroll
    for (int k = 1; k < PAIRS_PER_THREAD; k++) {
        int ii = ia[k - 1], jj = ja[k - 1] + 1;
        if (jj == N_FEAT) { ii++; jj = ii + 1; }
        ia[k] = ii; ja[k] = jj;
    }

    const float4 w4 = *(const float4*)(w + p0);

    #pragma unroll
    for (int b = 0; b < TB; b++) {
        const float* xr = xs + b * N_FEAT;
        float4 o;
        o.x = xr[ia[0]] * xr[ja[0]] * w4.x;
        o.y = xr[ia[1]] * xr[ja[1]] * w4.y;
        o.z = xr[ia[2]] * xr[ja[2]] * w4.z;
        o.w = xr[ia[3]] * xr[ja[3]] * w4.w;
        float4* dst = (float4*)(out + (size_t)(b0 + b) * N_PAIRS + p0);
        __stcs(dst, o);   // streaming store: don't pollute L2 (x/w stay resident)
    }
}

extern "C" void kernel_launch(void* const* d_in, const int* in_sizes, int n_in,
                              void* d_out, int out_size)
{
    const float* x = (const float*)d_in[0];
    const float* w = (const float*)d_in[1];
    float* out = (float*)d_out;

    dim3 grid((N_PAIRS + PAIRS_PER_BLOCK - 1) / PAIRS_PER_BLOCK, 1024 / TB);
    wide_layer_kernel<<<grid, THREADS>>>(x, w, out);
}

// round 2
// speedup vs baseline: 1.0581x; 1.0581x over previous
#include <cuda_runtime.h>
#include <cstdint>

#define N_FEAT 512
#define N_PAIRS (N_FEAT * (N_FEAT - 1) / 2)   // 130816 (divisible by 4)
#define TB 8            // batch rows per block
#define THREADS 256
#define PAIRS_PER_THREAD 4
#define PAIRS_PER_BLOCK (THREADS * PAIRS_PER_THREAD)  // 1024

// Bank-permutation: feature f stored at word perm(f).
// For lane-stride-4 access patterns (j = j0 + 4*lane), perm(j) mod 32 has
// lane stride 1 -> conflict-free scalar LDS.
__device__ __forceinline__ int perm(int f) {
    return (f >> 2) | ((f & 3) << 7);
}

// offset of first pair with row index i in the upper-triangular (k=1) ordering
__device__ __forceinline__ int tri_off(int i) {
    return (i * (2 * N_FEAT - 1 - i)) >> 1;
}

__device__ __forceinline__ void pair_from_p(int p, int& i, int& j) {
    float t = (float)N_FEAT - 0.5f;
    float d = t * t - 2.0f * (float)p;
    d = d > 0.0f ? d : 0.0f;
    int ii = (int)floorf(t - sqrtf(d));
    if (ii < 0) ii = 0;
    if (ii > N_FEAT - 2) ii = N_FEAT - 2;
    while (ii < N_FEAT - 2 && tri_off(ii + 1) <= p) ii++;
    while (ii > 0 && tri_off(ii) > p) ii--;
    i = ii;
    j = ii + 1 + (p - tri_off(ii));
}

__global__ void __launch_bounds__(THREADS, 4)
wide_layer_kernel(const float* __restrict__ x,
                  const float* __restrict__ w,
                  float* __restrict__ out)
{
    __shared__ float xs[TB * N_FEAT];   // 16 KB, bank-permuted per row

    const int tid = threadIdx.x;
    const int b0  = blockIdx.y * TB;

    // Cooperative load of the x tile, scattered into the permuted layout.
    // Each thread reads one float4 (features 4c..4c+3 of some row) and writes
    // 4 scalars; per STS instruction, lanes hit bank-stride-1 -> conflict-free.
    {
        const float4* xg = (const float4*)(x + (size_t)b0 * N_FEAT);
        #pragma unroll
        for (int k = 0; k < (TB * N_FEAT / 4) / THREADS; k++) {
            int v = tid + k * THREADS;          // float4 index within tile
            int row = v >> 7;                   // / (N_FEAT/4)
            int c   = v & 127;                  // float4 col
            float4 val = xg[v];
            float* dst = xs + row * N_FEAT;
            int f = c * 4;
            dst[perm(f + 0)] = val.x;
            dst[perm(f + 1)] = val.y;
            dst[perm(f + 2)] = val.z;
            dst[perm(f + 3)] = val.w;
        }
    }
    __syncthreads();

    const int p0 = blockIdx.x * PAIRS_PER_BLOCK + tid * PAIRS_PER_THREAD;
    if (p0 >= N_PAIRS) return;

    // compute the 4 (i,j) pairs once per thread
    int i0, j0;
    pair_from_p(p0, i0, j0);
    int ip[PAIRS_PER_THREAD], jp[PAIRS_PER_THREAD];
    {
        int ii = i0, jj = j0;
        #pragma unroll
        for (int k = 0; k < PAIRS_PER_THREAD; k++) {
            ip[k] = perm(ii);
            jp[k] = perm(jj);
            jj++;
            if (jj == N_FEAT) { ii++; jj = ii + 1; }
        }
    }

    const float4 w4 = *(const float4*)(w + p0);

    #pragma unroll
    for (int b = 0; b < TB; b++) {
        const float* xr = xs + b * N_FEAT;
        float4 o;
        o.x = xr[ip[0]] * xr[jp[0]] * w4.x;
        o.y = xr[ip[1]] * xr[jp[1]] * w4.y;
        o.z = xr[ip[2]] * xr[jp[2]] * w4.z;
        o.w = xr[ip[3]] * xr[jp[3]] * w4.w;
        float4* dst = (float4*)(out + (size_t)(b0 + b) * N_PAIRS + p0);
        __stcs(dst, o);   // streaming store: keep x/w resident in L2
    }
}

extern "C" void kernel_launch(void* const* d_in, const int* in_sizes, int n_in,
                              void* d_out, int out_size)
{
    const float* x = (const float*)d_in[0];
    const float* w = (const float*)d_in[1];
    float* out = (float*)d_out;

    dim3 grid((N_PAIRS + PAIRS_PER_BLOCK - 1) / PAIRS_PER_BLOCK, 1024 / TB);
    wide_layer_kernel<<<grid, THREADS>>>(x, w, out);
}

// round 3
// speedup vs baseline: 1.2711x; 1.2014x over previous
#include <cuda_runtime.h>
#include <cstdint>

#define N_FEAT 512
#define N_PAIRS (N_FEAT * (N_FEAT - 1) / 2)   // 130816 (divisible by 4)
#define TB 8            // batch rows per block
#define THREADS 256
#define PAIRS_PER_THREAD 4
#define PAIRS_PER_BLOCK (THREADS * PAIRS_PER_THREAD)  // 1024

// Bank-permutation: feature f stored at word perm(f).
// For lane-stride-4 access patterns (j = j0 + 4*lane), perm(j) mod 32 has
// lane stride 1 -> conflict-free scalar LDS.
__device__ __forceinline__ int perm(int f) {
    return (f >> 2) | ((f & 3) << 7);
}

// offset of first pair with row index i in the upper-triangular (k=1) ordering
__device__ __forceinline__ int tri_off(int i) {
    return (i * (2 * N_FEAT - 1 - i)) >> 1;
}

__device__ __forceinline__ void pair_from_p(int p, int& i, int& j) {
    float t = (float)N_FEAT - 0.5f;
    float d = t * t - 2.0f * (float)p;
    d = d > 0.0f ? d : 0.0f;
    int ii = (int)floorf(t - sqrtf(d));
    if (ii < 0) ii = 0;
    if (ii > N_FEAT - 2) ii = N_FEAT - 2;
    while (ii < N_FEAT - 2 && tri_off(ii + 1) <= p) ii++;
    while (ii > 0 && tri_off(ii) > p) ii--;
    i = ii;
    j = ii + 1 + (p - tri_off(ii));
}

__global__ void __launch_bounds__(THREADS, 6)
wide_layer_kernel(const float* __restrict__ x,
                  const float* __restrict__ w,
                  float* __restrict__ out)
{
    __shared__ float xs[TB * N_FEAT];   // 16 KB, bank-permuted per row

    const int tid = threadIdx.x;
    const int b0  = blockIdx.y * TB;

    // Cooperative load of the x tile, scattered into the permuted layout.
    {
        const float4* xg = (const float4*)(x + (size_t)b0 * N_FEAT);
        #pragma unroll
        for (int k = 0; k < (TB * N_FEAT / 4) / THREADS; k++) {
            int v = tid + k * THREADS;          // float4 index within tile
            int row = v >> 7;                   // / (N_FEAT/4)
            int c   = v & 127;                  // float4 col
            float4 val = xg[v];
            float* dst = xs + row * N_FEAT;
            int f = c * 4;
            dst[perm(f + 0)] = val.x;
            dst[perm(f + 1)] = val.y;
            dst[perm(f + 2)] = val.z;
            dst[perm(f + 3)] = val.w;
        }
    }
    __syncthreads();

    const int p0 = blockIdx.x * PAIRS_PER_BLOCK + tid * PAIRS_PER_THREAD;
    if (p0 >= N_PAIRS) return;

    // compute the 4 (i,j) pairs once per thread (pre-permuted smem indices)
    int ip[PAIRS_PER_THREAD], jp[PAIRS_PER_THREAD];
    {
        int ii, jj;
        pair_from_p(p0, ii, jj);
        #pragma unroll
        for (int k = 0; k < PAIRS_PER_THREAD; k++) {
            ip[k] = perm(ii);
            jp[k] = perm(jj);
            jj++;
            if (jj == N_FEAT) { ii++; jj = ii + 1; }
        }
    }

    const float4 w4 = *(const float4*)(w + p0);

    // incremental store pointer: one add per row instead of full addressing
    float4* dst = (float4*)(out + (size_t)b0 * N_PAIRS + p0);
    const size_t dstride = N_PAIRS / 4;   // float4 elements per output row

    const float* xr = xs;
    #pragma unroll
    for (int b = 0; b < TB; b++) {
        float4 o;
        o.x = xr[ip[0]] * xr[jp[0]] * w4.x;
        o.y = xr[ip[1]] * xr[jp[1]] * w4.y;
        o.z = xr[ip[2]] * xr[jp[2]] * w4.z;
        o.w = xr[ip[3]] * xr[jp[3]] * w4.w;
        __stcs(dst, o);   // streaming store: keep x/w resident in L2
        dst += dstride;
        xr  += N_FEAT;
    }
}

extern "C" void kernel_launch(void* const* d_in, const int* in_sizes, int n_in,
                              void* d_out, int out_size)
{
    const float* x = (const float*)d_in[0];
    const float* w = (const float*)d_in[1];
    float* out = (float*)d_out;

    dim3 grid((N_PAIRS + PAIRS_PER_BLOCK - 1) / PAIRS_PER_BLOCK, 1024 / TB);
    wide_layer_kernel<<<grid, THREADS>>>(x, w, out);
}

// round 4
// speedup vs baseline: 1.3283x; 1.0450x over previous
#include <cuda_runtime.h>
#include <cstdint>

#define N_FEAT 512
#define N_PAIRS (N_FEAT * (N_FEAT - 1) / 2)   // 130816 (divisible by 4)
#define TB 8            // batch rows per block
#define THREADS 256
#define PAIRS_PER_THREAD 4
#define PAIRS_PER_BLOCK (THREADS * PAIRS_PER_THREAD)  // 1024

// Bank-permutation: feature f stored at word perm(f).
// For lane-stride-4 access patterns (j = j0 + 4*lane), perm(j) mod 32 has
// lane stride 1 -> conflict-free scalar LDS.
__device__ __forceinline__ int perm(int f) {
    return (f >> 2) | ((f & 3) << 7);
}

// offset of first pair with row index i in the upper-triangular (k=1) ordering
__device__ __forceinline__ int tri_off(int i) {
    return (i * (2 * N_FEAT - 1 - i)) >> 1;
}

__device__ __forceinline__ void pair_from_p(int p, int& i, int& j) {
    float t = (float)N_FEAT - 0.5f;
    float d = t * t - 2.0f * (float)p;
    d = d > 0.0f ? d : 0.0f;
    int ii = (int)floorf(t - sqrtf(d));
    if (ii < 0) ii = 0;
    if (ii > N_FEAT - 2) ii = N_FEAT - 2;
    while (ii < N_FEAT - 2 && tri_off(ii + 1) <= p) ii++;
    while (ii > 0 && tri_off(ii) > p) ii--;
    i = ii;
    j = ii + 1 + (p - tri_off(ii));
}

__global__ void __launch_bounds__(THREADS, 6)
wide_layer_kernel(const float* __restrict__ x,
                  const float* __restrict__ w,
                  float* __restrict__ out)
{
    __shared__ float xs[TB * N_FEAT];   // 16 KB, bank-permuted per row

    const int tid = threadIdx.x;
    const int b0  = blockIdx.y * TB;

    // Cooperative load of the x tile, scattered into the permuted layout.
    {
        const float4* xg = (const float4*)(x + (size_t)b0 * N_FEAT);
        #pragma unroll
        for (int k = 0; k < (TB * N_FEAT / 4) / THREADS; k++) {
            int v = tid + k * THREADS;          // float4 index within tile
            int row = v >> 7;                   // / (N_FEAT/4)
            int c   = v & 127;                  // float4 col
            float4 val = xg[v];
            float* dst = xs + row * N_FEAT;
            int f = c * 4;
            dst[perm(f + 0)] = val.x;
            dst[perm(f + 1)] = val.y;
            dst[perm(f + 2)] = val.z;
            dst[perm(f + 3)] = val.w;
        }
    }
    __syncthreads();

    const int p0 = blockIdx.x * PAIRS_PER_BLOCK + tid * PAIRS_PER_THREAD;
    if (p0 >= N_PAIRS) return;

    // compute the 4 (i,j) pairs once per thread (pre-permuted smem indices)
    int ip[PAIRS_PER_THREAD], jp[PAIRS_PER_THREAD];
    {
        int ii, jj;
        pair_from_p(p0, ii, jj);
        #pragma unroll
        for (int k = 0; k < PAIRS_PER_THREAD; k++) {
            ip[k] = perm(ii);
            jp[k] = perm(jj);
            jj++;
            if (jj == N_FEAT) { ii++; jj = ii + 1; }
        }
    }

    // i-side selection plan: 4 pairs span at most 2 distinct i values, except
    // one thread per p-block (rows 508/509/510) which gets a predicated LDS.
    const bool s1   = (ip[1] == ip[0]);          // k=1 uses xi_a else xi_b
    const bool s2   = (ip[2] == ip[0]);
    const bool odd1 = (ip[1] != ip[0]) && (ip[1] != ip[3]);  // 3-row span (rare)
    const bool odd2 = (ip[2] != ip[0]) && (ip[2] != ip[3]);

    const float4 w4 = *(const float4*)(w + p0);

    // incremental store pointer: one add per row instead of full addressing
    float4* dst = (float4*)(out + (size_t)b0 * N_PAIRS + p0);
    const size_t dstride = N_PAIRS / 4;   // float4 elements per output row

    const float* xr = xs;
    #pragma unroll
    for (int b = 0; b < TB; b++) {
        float xi_a = xr[ip[0]];               // broadcast LDS
        float xi_b = xr[ip[3]];               // broadcast LDS
        float x1 = s1 ? xi_a : xi_b;
        float x2 = s2 ? xi_a : xi_b;
        if (odd1) x1 = xr[ip[1]];             // rare fallback (1 thread/p-block)
        if (odd2) x2 = xr[ip[2]];
        float4 o;
        o.x = xi_a * xr[jp[0]] * w4.x;
        o.y = x1   * xr[jp[1]] * w4.y;
        o.z = x2   * xr[jp[2]] * w4.z;
        o.w = xi_b * xr[jp[3]] * w4.w;
        __stcs(dst, o);   // streaming store: keep x/w resident in L2
        dst += dstride;
        xr  += N_FEAT;
    }
}

extern "C" void kernel_launch(void* const* d_in, const int* in_sizes, int n_in,
                              void* d_out, int out_size)
{
    const float* x = (const float*)d_in[0];
    const float* w = (const float*)d_in[1];
    float* out = (float*)d_out;

    dim3 grid((N_PAIRS + PAIRS_PER_BLOCK - 1) / PAIRS_PER_BLOCK, 1024 / TB);
    wide_layer_kernel<<<grid, THREADS>>>(x, w, out);
}